// round 13
// baseline (speedup 1.0000x reference)
#include <cuda_runtime.h>
#include <cstdint>

// Problem constants (fixed-shape problem)
#define WIN   48
#define DIN   64
#define DOUT  128
#define BATCH 4096
#define NSEG  (BATCH * WIN)      // 196608 segments
#define CAP   64                 // bucket slots per segment

#define A_PAD 68                 // means row stride: bank 4g+tig bijective
#define WH_PAD 72                // half-W row stride: 72%32=8 -> bank 8tig+g bijective

// Scratch
__device__ int      g_cur[NSEG];
__device__ int      g_bucket[NSEG * CAP];
__device__ float    g_mean[NSEG * DIN];
__device__ uint32_t g_whi[DIN * DOUT];   // tf32 hi plane of W (64KB, L2-resident)
__device__ uint32_t g_wlo[DIN * DOUT];   // tf32 lo plane of W

__device__ __forceinline__ uint32_t tf32_bits(float x) {
    uint32_t u;
    asm("cvt.rna.tf32.f32 %0, %1;" : "=r"(u) : "f"(x));
    return u;
}
__device__ __forceinline__ void mma_tf32(float* c, const uint32_t* a,
                                         const uint32_t* b) {
    asm("mma.sync.aligned.m16n8k8.row.col.f32.tf32.tf32.f32 "
        "{%0,%1,%2,%3}, {%4,%5,%6,%7}, {%8,%9}, {%0,%1,%2,%3};"
        : "+f"(c[0]), "+f"(c[1]), "+f"(c[2]), "+f"(c[3])
        : "r"(a[0]), "r"(a[1]), "r"(a[2]), "r"(a[3]), "r"(b[0]), "r"(b[1]));
}

// ---------------------------------------------------------------------------
// 0) split W into tf32 hi/lo planes (once; tiny)
// ---------------------------------------------------------------------------
__global__ void wsplit_kernel(const float* __restrict__ Wm) {
    int i = blockIdx.x * blockDim.x + threadIdx.x;
    if (i < DIN * DOUT) {
        float w = Wm[i];
        uint32_t hi = tf32_bits(w);
        g_whi[i] = hi;
        g_wlo[i] = tf32_bits(w - __uint_as_float(hi));
    }
}

// ---------------------------------------------------------------------------
// 1) zero cursors
// ---------------------------------------------------------------------------
__global__ void zero_cur_kernel() {
    int i = blockIdx.x * blockDim.x + threadIdx.x;
    if (i < NSEG) g_cur[i] = 0;
}

// ---------------------------------------------------------------------------
// 2) scatter event indices into fixed-capacity buckets (bump allocation)
// ---------------------------------------------------------------------------
__global__ void scatter_idx_kernel(const int* __restrict__ bi,
                                   const int* __restrict__ wi, int n) {
    int i = blockIdx.x * blockDim.x + threadIdx.x;
    if (i >= n) return;
    int seg = bi[i] * WIN + wi[i];
    int pos = atomicAdd(&g_cur[seg], 1);
    if (pos < CAP) g_bucket[(seg << 6) + pos] = i;
}

// ---------------------------------------------------------------------------
// 3) gather-reduce: ONE warp per segment, burst loads (UNCHANGED — profiled
//    at 74% DRAM, near its random-gather bandwidth floor)
// ---------------------------------------------------------------------------
__global__ __launch_bounds__(256) void reduce_kernel(const float* __restrict__ in) {
    int seg  = (blockIdx.x * blockDim.x + threadIdx.x) >> 5;
    int lane = threadIdx.x & 31;
    if (seg >= NSEG) return;

    int cnt = __ldg(&g_cur[seg]);
    if (cnt > CAP) cnt = CAP;
    float* dst = g_mean + (size_t)seg * DIN + lane * 2;
    if (cnt == 0) {
        dst[0] = 0.f;
        dst[1] = 0.f;
        return;
    }
    int base = seg << 6;
    int last = cnt - 1;

    int idx[16];
    #pragma unroll
    for (int t = 0; t < 16; t++)
        idx[t] = __ldg(&g_bucket[base + (t < last ? t : last)]);

    float2 v[16];
    #pragma unroll
    for (int t = 0; t < 16; t++) {
        v[t] = make_float2(0.f, 0.f);
        if (t < cnt)
            v[t] = *reinterpret_cast<const float2*>(
                in + (size_t)idx[t] * DIN + lane * 2);
    }

    float a0 = 0.f, a1 = 0.f;
    #pragma unroll
    for (int t = 0; t < 16; t += 4) {
        a0 += (v[t].x + v[t+1].x) + (v[t+2].x + v[t+3].x);
        a1 += (v[t].y + v[t+1].y) + (v[t+2].y + v[t+3].y);
    }

    for (int t = 16; t < cnt; t++) {
        int e = __ldg(&g_bucket[base + t]);
        float2 w = *reinterpret_cast<const float2*>(
            in + (size_t)e * DIN + lane * 2);
        a0 += w.x;
        a1 += w.y;
    }

    float inv = 1.f / (float)cnt;
    dst[0] = a0 * inv;
    dst[1] = a1 * inv;
}

// ---------------------------------------------------------------------------
// 4) split-N tensor-core GEMM: 2 blocks per batch, each owns 64 d-columns.
//    3xTF32, conversions hoisted (W planes global, A split once in smem).
//    Dynamic smem (words):
//      s_ahi [48*68]  @ 0        (13056 B)   fp32 means then tf32-hi in place
//      s_alo [48*68]  @ 13056    (13056 B)
//      s_whi [64*72]  @ 26112    (18432 B)
//      s_wlo [64*72]  @ 44544    (18432 B)
//      s_b   [64]     @ 62976
//      s_has [48]     @ 63232    -> total 63424 B  (3 blocks/SM)
//    Out staging [64][49] (12544 B) reuses the base region after the loop.
// ---------------------------------------------------------------------------
#define SMEM_TOTAL 63680

__global__ __launch_bounds__(256) void pool_gemm_kernel(
    const float* __restrict__ bias,
    float*       __restrict__ out)    // [BATCH][DOUT][WIN]
{
    extern __shared__ char smem[];
    float*    s_a   = reinterpret_cast<float*>(smem);
    uint32_t* s_ahi = reinterpret_cast<uint32_t*>(smem);
    uint32_t* s_alo = s_ahi + WIN * A_PAD;
    uint32_t* s_whi = s_alo + WIN * A_PAD;
    uint32_t* s_wlo = s_whi + DIN * WH_PAD;
    float*    s_b   = reinterpret_cast<float*>(s_wlo + DIN * WH_PAD);
    float*    s_has = s_b + 64;
    float*    s_out = reinterpret_cast<float*>(smem);   // staging [64][49]

    int bx  = blockIdx.x;
    int b   = bx >> 1;            // batch
    int nh  = bx & 1;             // which 64-column half
    int n_base = nh * 64;
    int tid = threadIdx.x;
    int lane = tid & 31;
    int wg   = tid >> 5;
    int g    = lane >> 2;     // 0..7
    int tig  = lane & 3;      // 0..3

    if (tid < WIN) s_has[tid] = (g_cur[b * WIN + tid] > 0) ? 1.f : 0.f;
    if (tid < 64)  s_b[tid] = bias[n_base + tid];

    // ---- load this half's W hi/lo planes (16 uint4 per row) ----
    {
        #pragma unroll
        for (int i = tid; i < DIN * 16; i += 256) {
            int row = i >> 4;
            int c4  = i & 15;
            int gidx = (row * DOUT + n_base) / 4 + c4;
            *reinterpret_cast<uint4*>(s_whi + row * WH_PAD + c4 * 4) =
                reinterpret_cast<const uint4*>(g_whi)[gidx];
            *reinterpret_cast<uint4*>(s_wlo + row * WH_PAD + c4 * 4) =
                reinterpret_cast<const uint4*>(g_wlo)[gidx];
        }
    }
    // ---- load means into padded smem (fp32, into s_ahi region) ----
    {
        const float4* m4 = reinterpret_cast<const float4*>(
            g_mean + (size_t)b * WIN * DIN);
        #pragma unroll
        for (int i = tid; i < WIN * DIN / 4; i += 256) {
            int row = i >> 4;
            int c4  = i & 15;
            *reinterpret_cast<float4*>(s_a + row * A_PAD + c4 * 4) = m4[i];
        }
    }
    __syncthreads();

    // ---- split A into tf32 hi (in place) / lo, once per element ----
    #pragma unroll
    for (int i = tid; i < WIN * DIN; i += 256) {
        int row = i >> 6;
        int col = i & 63;
        int a = row * A_PAD + col;
        float v = s_a[a];
        uint32_t hi = tf32_bits(v);
        s_ahi[a] = hi;
        s_alo[a] = tf32_bits(v - __uint_as_float(hi));
    }
    __syncthreads();

    // ---- accumulators: 3 m-tiles x 1 n-tile x 4 ----
    float acc[3][4];
    #pragma unroll
    for (int mt = 0; mt < 3; mt++)
        #pragma unroll
        for (int q = 0; q < 4; q++) acc[mt][q] = 0.f;

    int n0 = wg * 8;   // this warp's n8 tile within the half

    #pragma unroll
    for (int ks = 0; ks < 8; ks++) {
        int k0 = ks * 8;

        uint32_t ahi[3][4], alo[3][4];
        #pragma unroll
        for (int mt = 0; mt < 3; mt++) {
            int base = (mt * 16 + g) * A_PAD + k0 + tig;
            ahi[mt][0] = s_ahi[base];
            ahi[mt][1] = s_ahi[base + 8 * A_PAD];
            ahi[mt][2] = s_ahi[base + 4];
            ahi[mt][3] = s_ahi[base + 8 * A_PAD + 4];
            alo[mt][0] = s_alo[base];
            alo[mt][1] = s_alo[base + 8 * A_PAD];
            alo[mt][2] = s_alo[base + 4];
            alo[mt][3] = s_alo[base + 8 * A_PAD + 4];
        }

        uint32_t bhi[2], blo[2];
        {
            int base = (k0 + tig) * WH_PAD + n0 + g;
            bhi[0] = s_whi[base];
            bhi[1] = s_whi[base + 4 * WH_PAD];
            blo[0] = s_wlo[base];
            blo[1] = s_wlo[base + 4 * WH_PAD];
        }

        #pragma unroll
        for (int mt = 0; mt < 3; mt++) {
            mma_tf32(acc[mt], ahi[mt], bhi);
            mma_tf32(acc[mt], ahi[mt], blo);
            mma_tf32(acc[mt], alo[mt], bhi);
        }
    }

    __syncthreads();   // done with A/W smem; reuse as staging

    // ---- stage results as out[d_local][w] pad-49 (+bias if nonempty) ----
    #pragma unroll
    for (int mt = 0; mt < 3; mt++) {
        int w0 = mt * 16 + g;
        int w1 = w0 + 8;
        float h0 = s_has[w0];
        float h1 = s_has[w1];
        int d = n0 + tig * 2;
        float bx2 = s_b[d], by2 = s_b[d + 1];
        s_out[(d    ) * 49 + w0] = acc[mt][0] + h0 * bx2;
        s_out[(d + 1) * 49 + w0] = acc[mt][1] + h0 * by2;
        s_out[(d    ) * 49 + w1] = acc[mt][2] + h1 * bx2;
        s_out[(d + 1) * 49 + w1] = acc[mt][3] + h1 * by2;
    }
    __syncthreads();

    // ---- coalesced float4 store: 64 d x 48 w = 768 float4 ----
    float* obase = out + (size_t)b * DOUT * WIN + n_base * WIN;
    #pragma unroll
    for (int it = 0; it < 3; it++) {
        int j = it * 1024 + tid * 4;   // 48 % 4 == 0 -> all 4 elems share d
        int d = j / 48;
        int w = j - d * 48;
        const float* src = s_out + d * 49 + w;
        float4 v = make_float4(src[0], src[1], src[2], src[3]);
        *reinterpret_cast<float4*>(obase + j) = v;
    }
}

// ---------------------------------------------------------------------------
extern "C" void kernel_launch(void* const* d_in, const int* in_sizes, int n_in,
                              void* d_out, int out_size) {
    const float* input = (const float*)d_in[0];
    const float* Wm    = (const float*)d_in[1];
    const float* bias  = (const float*)d_in[2];

    const int* bi;
    const int* wi;
    int n_events;
    if (n_in >= 6 && in_sizes[3] == 1) {
        bi = (const int*)d_in[4];
        wi = (const int*)d_in[5];
        n_events = in_sizes[4];
    } else {
        bi = (const int*)d_in[3];
        wi = (const int*)d_in[4];
        n_events = in_sizes[3];
    }

    int eb = (n_events + 255) / 256;

    static bool attr_set = false;
    if (!attr_set) {
        cudaFuncSetAttribute(pool_gemm_kernel,
                             cudaFuncAttributeMaxDynamicSharedMemorySize,
                             SMEM_TOTAL);
        attr_set = true;
    }

    wsplit_kernel<<<(DIN * DOUT + 255) / 256, 256>>>(Wm);
    zero_cur_kernel<<<(NSEG + 255) / 256, 256>>>();
    scatter_idx_kernel<<<eb, 256>>>(bi, wi, n_events);
    reduce_kernel<<<NSEG / 8, 256>>>(input);
    pool_gemm_kernel<<<BATCH * 2, 256, SMEM_TOTAL>>>(bias, (float*)d_out);
}

// round 15
// speedup vs baseline: 1.2097x; 1.2097x over previous
#include <cuda_runtime.h>
#include <cstdint>

// Problem constants (fixed-shape problem)
#define WIN   48
#define DIN   64
#define DOUT  128
#define BATCH 4096
#define NSEG  (BATCH * WIN)      // 196608 segments
#define CAP   64                 // bucket slots per segment

#define A_PAD 68                 // means row stride: bank 4g+tig bijective
#define W_PAD 136                // W row stride: bank 8tig+g bijective

// Scratch
__device__ int   g_cur[NSEG];
__device__ int   g_bucket[NSEG * CAP];
__device__ float g_mean[NSEG * DIN];

__device__ __forceinline__ uint32_t tf32_bits(float x) {
    uint32_t u;
    asm("cvt.rna.tf32.f32 %0, %1;" : "=r"(u) : "f"(x));
    return u;
}
__device__ __forceinline__ void mma_tf32(float* c, const uint32_t* a,
                                         const uint32_t* b) {
    asm("mma.sync.aligned.m16n8k8.row.col.f32.tf32.tf32.f32 "
        "{%0,%1,%2,%3}, {%4,%5,%6,%7}, {%8,%9}, {%0,%1,%2,%3};"
        : "+f"(c[0]), "+f"(c[1]), "+f"(c[2]), "+f"(c[3])
        : "r"(a[0]), "r"(a[1]), "r"(a[2]), "r"(a[3]), "r"(b[0]), "r"(b[1]));
}

// ---------------------------------------------------------------------------
// 1) zero cursors
// ---------------------------------------------------------------------------
__global__ void zero_cur_kernel() {
    int i = blockIdx.x * blockDim.x + threadIdx.x;
    if (i < NSEG) g_cur[i] = 0;
}

// ---------------------------------------------------------------------------
// 2) scatter event indices into fixed-capacity buckets (bump allocation)
// ---------------------------------------------------------------------------
__global__ void scatter_idx_kernel(const int* __restrict__ bi,
                                   const int* __restrict__ wi, int n) {
    int i = blockIdx.x * blockDim.x + threadIdx.x;
    if (i >= n) return;
    int seg = bi[i] * WIN + wi[i];
    int pos = atomicAdd(&g_cur[seg], 1);
    if (pos < CAP) g_bucket[(seg << 6) + pos] = i;
}

// ---------------------------------------------------------------------------
// 3) gather-reduce: ONE warp per segment, burst loads (UNCHANGED — profiled
//    at 74% DRAM, near its random-gather bandwidth floor)
// ---------------------------------------------------------------------------
__global__ __launch_bounds__(256) void reduce_kernel(const float* __restrict__ in) {
    int seg  = (blockIdx.x * blockDim.x + threadIdx.x) >> 5;
    int lane = threadIdx.x & 31;
    if (seg >= NSEG) return;

    int cnt = __ldg(&g_cur[seg]);
    if (cnt > CAP) cnt = CAP;
    float* dst = g_mean + (size_t)seg * DIN + lane * 2;
    if (cnt == 0) {
        dst[0] = 0.f;
        dst[1] = 0.f;
        return;
    }
    int base = seg << 6;
    int last = cnt - 1;

    int idx[16];
    #pragma unroll
    for (int t = 0; t < 16; t++)
        idx[t] = __ldg(&g_bucket[base + (t < last ? t : last)]);

    float2 v[16];
    #pragma unroll
    for (int t = 0; t < 16; t++) {
        v[t] = make_float2(0.f, 0.f);
        if (t < cnt)
            v[t] = *reinterpret_cast<const float2*>(
                in + (size_t)idx[t] * DIN + lane * 2);
    }

    float a0 = 0.f, a1 = 0.f;
    #pragma unroll
    for (int t = 0; t < 16; t += 4) {
        a0 += (v[t].x + v[t+1].x) + (v[t+2].x + v[t+3].x);
        a1 += (v[t].y + v[t+1].y) + (v[t+2].y + v[t+3].y);
    }

    for (int t = 16; t < cnt; t++) {
        int e = __ldg(&g_bucket[base + t]);
        float2 w = *reinterpret_cast<const float2*>(
            in + (size_t)e * DIN + lane * 2);
        a0 += w.x;
        a1 += w.y;
    }

    float inv = 1.f / (float)cnt;
    dst[0] = a0 * inv;
    dst[1] = a1 * inv;
}

// ---------------------------------------------------------------------------
// 4) per-batch tensor-core GEMM (3xTF32): EXACT round-11 structure, but the
//    A hi/lo split is done ONCE cooperatively in smem instead of per-warp
//    in the mainloop. B (W) conversions stay in-loop.
//    Dynamic smem:
//      s_a/s_ahi [48*68]  @ 0       (13056 B)  fp32 means -> tf32 hi in place
//      s_alo     [48*68]  @ 13056   (13056 B)
//      s_w       [64*136] @ 26112   (34816 B)  fp32 W; reused as out[128][49]
//      s_b       [128]    @ 60928
//      s_has     [48]     @ 61440   -> total 61632 B (3 blocks/SM, same as R11)
// ---------------------------------------------------------------------------
#define SMEM_TOTAL 61696

__global__ __launch_bounds__(256) void pool_gemm_kernel(
    const float* __restrict__ Wm,     // [DIN][DOUT] row-major (k-major)
    const float* __restrict__ bias,
    float*       __restrict__ out)    // [BATCH][DOUT][WIN]
{
    extern __shared__ char smem[];
    float*    s_a   = reinterpret_cast<float*>(smem);
    uint32_t* s_ahi = reinterpret_cast<uint32_t*>(smem);
    uint32_t* s_alo = s_ahi + WIN * A_PAD;
    float*    s_w   = reinterpret_cast<float*>(s_alo + WIN * A_PAD);
    float*    s_b   = s_w + DIN * W_PAD;
    float*    s_has = s_b + DOUT;
    float*    s_out = s_w;            // staging [128][49] reuses W region

    int b   = blockIdx.x;
    int tid = threadIdx.x;
    int lane = tid & 31;
    int wg   = tid >> 5;
    int g    = lane >> 2;     // group id 0..7
    int tig  = lane & 3;      // thread in group 0..3

    if (tid < WIN) s_has[tid] = (g_cur[b * WIN + tid] > 0) ? 1.f : 0.f;
    if (tid < DOUT) s_b[tid] = bias[tid];

    // ---- load W into padded smem (fp32, row stride 136) ----
    {
        const float4* w4 = reinterpret_cast<const float4*>(Wm);
        #pragma unroll
        for (int i = tid; i < DIN * DOUT / 4; i += 256) {
            int row = i >> 5;
            int c4  = i & 31;
            *reinterpret_cast<float4*>(s_w + row * W_PAD + c4 * 4) = w4[i];
        }
    }
    // ---- load means into padded smem ----
    {
        const float4* m4 = reinterpret_cast<const float4*>(
            g_mean + (size_t)b * WIN * DIN);
        #pragma unroll
        for (int i = tid; i < WIN * DIN / 4; i += 256) {
            int row = i >> 4;
            int c4  = i & 15;
            *reinterpret_cast<float4*>(s_a + row * A_PAD + c4 * 4) = m4[i];
        }
    }
    __syncthreads();

    // ---- split A into tf32 hi (in place) / lo — once per element ----
    #pragma unroll
    for (int i = tid; i < WIN * DIN; i += 256) {
        int row = i >> 6;
        int col = i & 63;
        int a = row * A_PAD + col;
        float v = s_a[a];
        uint32_t hi = tf32_bits(v);
        s_ahi[a] = hi;
        s_alo[a] = tf32_bits(v - __uint_as_float(hi));
    }
    __syncthreads();

    // ---- accumulators: 3 m-tiles x 2 n-tiles x 4 ----
    float acc[3][2][4];
    #pragma unroll
    for (int mt = 0; mt < 3; mt++)
        #pragma unroll
        for (int nt = 0; nt < 2; nt++)
            #pragma unroll
            for (int q = 0; q < 4; q++) acc[mt][nt][q] = 0.f;

    int n0 = wg * 16;   // this warp's 16 output columns (2 n8 tiles)

    #pragma unroll
    for (int ks = 0; ks < 8; ks++) {
        int k0 = ks * 8;

        // ---- A fragments: plain LDS of pre-split planes ----
        uint32_t ahi[3][4], alo[3][4];
        #pragma unroll
        for (int mt = 0; mt < 3; mt++) {
            int base = (mt * 16 + g) * A_PAD + k0 + tig;
            ahi[mt][0] = s_ahi[base];
            ahi[mt][1] = s_ahi[base + 8 * A_PAD];
            ahi[mt][2] = s_ahi[base + 4];
            ahi[mt][3] = s_ahi[base + 8 * A_PAD + 4];
            alo[mt][0] = s_alo[base];
            alo[mt][1] = s_alo[base + 8 * A_PAD];
            alo[mt][2] = s_alo[base + 4];
            alo[mt][3] = s_alo[base + 8 * A_PAD + 4];
        }

        // ---- B fragments: fp32 LDS + in-loop tf32 split (cheap: 4 values) ----
        uint32_t bhi[2][2], blo[2][2];
        #pragma unroll
        for (int nt = 0; nt < 2; nt++) {
            const float* bb = s_w + (k0 + tig) * W_PAD + n0 + nt * 8 + g;
            float b0 = bb[0];
            float b1 = bb[4 * W_PAD];
            bhi[nt][0] = tf32_bits(b0);
            bhi[nt][1] = tf32_bits(b1);
            blo[nt][0] = tf32_bits(b0 - __uint_as_float(bhi[nt][0]));
            blo[nt][1] = tf32_bits(b1 - __uint_as_float(bhi[nt][1]));
        }

        // ---- 3xTF32 mma: hi*hi + hi*lo + lo*hi ----
        #pragma unroll
        for (int mt = 0; mt < 3; mt++)
            #pragma unroll
            for (int nt = 0; nt < 2; nt++) {
                mma_tf32(acc[mt][nt], ahi[mt], bhi[nt]);
                mma_tf32(acc[mt][nt], ahi[mt], blo[nt]);
                mma_tf32(acc[mt][nt], alo[mt], bhi[nt]);
            }
    }

    __syncthreads();   // all warps done reading s_w; reuse as staging

    // ---- stage results as out[d][w] pad-49 (+bias if nonempty) ----
    #pragma unroll
    for (int mt = 0; mt < 3; mt++) {
        int w0 = mt * 16 + g;
        int w1 = w0 + 8;
        float h0 = s_has[w0];
        float h1 = s_has[w1];
        #pragma unroll
        for (int nt = 0; nt < 2; nt++) {
            int d = n0 + nt * 8 + tig * 2;
            float bx = s_b[d], by = s_b[d + 1];
            s_out[(d    ) * 49 + w0] = acc[mt][nt][0] + h0 * bx;
            s_out[(d + 1) * 49 + w0] = acc[mt][nt][1] + h0 * by;
            s_out[(d    ) * 49 + w1] = acc[mt][nt][2] + h1 * bx;
            s_out[(d + 1) * 49 + w1] = acc[mt][nt][3] + h1 * by;
        }
    }
    __syncthreads();

    // ---- coalesced float4 store of out[b][d][w] ----
    float* obase = out + (size_t)b * DOUT * WIN;
    #pragma unroll
    for (int it = 0; it < 6; it++) {
        int j = it * 1024 + tid * 4;
        int d = j / 48;
        int w = j - d * 48;
        const float* src = s_out + d * 49 + w;
        float4 v = make_float4(src[0], src[1], src[2], src[3]);
        *reinterpret_cast<float4*>(obase + j) = v;
    }
}

// ---------------------------------------------------------------------------
extern "C" void kernel_launch(void* const* d_in, const int* in_sizes, int n_in,
                              void* d_out, int out_size) {
    const float* input = (const float*)d_in[0];
    const float* Wm    = (const float*)d_in[1];
    const float* bias  = (const float*)d_in[2];

    const int* bi;
    const int* wi;
    int n_events;
    if (n_in >= 6 && in_sizes[3] == 1) {
        bi = (const int*)d_in[4];
        wi = (const int*)d_in[5];
        n_events = in_sizes[4];
    } else {
        bi = (const int*)d_in[3];
        wi = (const int*)d_in[4];
        n_events = in_sizes[3];
    }

    int eb = (n_events + 255) / 256;

    static bool attr_set = false;
    if (!attr_set) {
        cudaFuncSetAttribute(pool_gemm_kernel,
                             cudaFuncAttributeMaxDynamicSharedMemorySize,
                             SMEM_TOTAL);
        attr_set = true;
    }

    zero_cur_kernel<<<(NSEG + 255) / 256, 256>>>();
    scatter_idx_kernel<<<eb, 256>>>(bi, wi, n_events);
    reduce_kernel<<<NSEG / 8, 256>>>(input);
    pool_gemm_kernel<<<BATCH, 256, SMEM_TOTAL>>>(Wm, bias, (float*)d_out);
}

// round 17
// speedup vs baseline: 1.2335x; 1.0197x over previous
#include <cuda_runtime.h>
#include <cstdint>

// Problem constants (fixed-shape problem)
#define WIN   48
#define DIN   64
#define DOUT  128
#define BATCH 4096
#define NSEG  (BATCH * WIN)      // 196608 segments
#define CAP   64                 // bucket slots per segment
#define A_PAD 68                 // temp means row stride (pre-pass only)

// Scratch
__device__ int      g_cur[NSEG];
__device__ int      g_bucket[NSEG * CAP];
__device__ float    g_mean[NSEG * DIN];
__device__ uint32_t g_whi_f[DIN * DOUT];   // W tf32 hi plane, FRAGMENT order
__device__ uint32_t g_wlo_f[DIN * DOUT];   // W tf32 lo plane, FRAGMENT order

__device__ __forceinline__ uint32_t tf32_bits(float x) {
    uint32_t u;
    asm("cvt.rna.tf32.f32 %0, %1;" : "=r"(u) : "f"(x));
    return u;
}
__device__ __forceinline__ void mma_tf32(float* c, const uint32_t* a,
                                         const uint32_t* b) {
    asm("mma.sync.aligned.m16n8k8.row.col.f32.tf32.tf32.f32 "
        "{%0,%1,%2,%3}, {%4,%5,%6,%7}, {%8,%9}, {%0,%1,%2,%3};"
        : "+f"(c[0]), "+f"(c[1]), "+f"(c[2]), "+f"(c[3])
        : "r"(a[0]), "r"(a[1]), "r"(a[2]), "r"(a[3]), "r"(b[0]), "r"(b[1]));
}

// ---------------------------------------------------------------------------
// 0) split W into tf32 hi/lo planes in MMA-FRAGMENT order (once; tiny).
//    Element i = ((wg*8 + ks)*32 + lane)*4 + q, where warp wg owns output
//    cols [wg*16, wg*16+16), q = nt*2 + j:
//      col = wg*16 + nt*8 + g,  k = ks*8 + tig + j*4   (g=lane>>2, tig=lane&3)
// ---------------------------------------------------------------------------
__global__ void wsplit_frag_kernel(const float* __restrict__ Wm) {
    int i = blockIdx.x * blockDim.x + threadIdx.x;
    if (i >= DIN * DOUT) return;
    int q    = i & 3;
    int lane = (i >> 2) & 31;
    int ks   = (i >> 7) & 7;
    int wg   = i >> 10;
    int g = lane >> 2, tig = lane & 3;
    int nt = q >> 1, j = q & 1;
    int col = wg * 16 + nt * 8 + g;
    int k   = ks * 8 + tig + j * 4;
    float w = Wm[k * DOUT + col];
    uint32_t hi = tf32_bits(w);
    g_whi_f[i] = hi;
    g_wlo_f[i] = tf32_bits(w - __uint_as_float(hi));
}

// ---------------------------------------------------------------------------
// 1) zero cursors
// ---------------------------------------------------------------------------
__global__ void zero_cur_kernel() {
    int i = blockIdx.x * blockDim.x + threadIdx.x;
    if (i < NSEG) g_cur[i] = 0;
}

// ---------------------------------------------------------------------------
// 2) scatter event indices into fixed-capacity buckets (bump allocation)
// ---------------------------------------------------------------------------
__global__ void scatter_idx_kernel(const int* __restrict__ bi,
                                   const int* __restrict__ wi, int n) {
    int i = blockIdx.x * blockDim.x + threadIdx.x;
    if (i >= n) return;
    int seg = bi[i] * WIN + wi[i];
    int pos = atomicAdd(&g_cur[seg], 1);
    if (pos < CAP) g_bucket[(seg << 6) + pos] = i;
}

// ---------------------------------------------------------------------------
// 3) gather-reduce: ONE warp per segment, burst loads (UNCHANGED — profiled
//    at 74% DRAM, near its random-gather bandwidth floor)
// ---------------------------------------------------------------------------
__global__ __launch_bounds__(256) void reduce_kernel(const float* __restrict__ in) {
    int seg  = (blockIdx.x * blockDim.x + threadIdx.x) >> 5;
    int lane = threadIdx.x & 31;
    if (seg >= NSEG) return;

    int cnt = __ldg(&g_cur[seg]);
    if (cnt > CAP) cnt = CAP;
    float* dst = g_mean + (size_t)seg * DIN + lane * 2;
    if (cnt == 0) {
        dst[0] = 0.f;
        dst[1] = 0.f;
        return;
    }
    int base = seg << 6;
    int last = cnt - 1;

    int idx[16];
    #pragma unroll
    for (int t = 0; t < 16; t++)
        idx[t] = __ldg(&g_bucket[base + (t < last ? t : last)]);

    float2 v[16];
    #pragma unroll
    for (int t = 0; t < 16; t++) {
        v[t] = make_float2(0.f, 0.f);
        if (t < cnt)
            v[t] = *reinterpret_cast<const float2*>(
                in + (size_t)idx[t] * DIN + lane * 2);
    }

    float a0 = 0.f, a1 = 0.f;
    #pragma unroll
    for (int t = 0; t < 16; t += 4) {
        a0 += (v[t].x + v[t+1].x) + (v[t+2].x + v[t+3].x);
        a1 += (v[t].y + v[t+1].y) + (v[t+2].y + v[t+3].y);
    }

    for (int t = 16; t < cnt; t++) {
        int e = __ldg(&g_bucket[base + t]);
        float2 w = *reinterpret_cast<const float2*>(
            in + (size_t)e * DIN + lane * 2);
        a0 += w.x;
        a1 += w.y;
    }

    float inv = 1.f / (float)cnt;
    dst[0] = a0 * inv;
    dst[1] = a1 * inv;
}

// ---------------------------------------------------------------------------
// 4) per-batch tensor-core GEMM (3xTF32), fragment-order operands:
//    A hi/lo pre-split into smem in fragment order (6 LDS.128 per k-step),
//    B hi/lo fragments loaded straight from L2-resident global planes
//    (2 LDG.128 per k-step). Zero conversions in the mainloop.
//    Static smem: fhi 12288 + flo 12288 + a_tmp 13056 + b 512 + has 192
//    = 38336 B. Out staging [128][49] (25088 B) reuses fhi/flo/a_tmp.
// ---------------------------------------------------------------------------
__global__ __launch_bounds__(256) void pool_gemm_kernel(
    const float* __restrict__ bias,
    float*       __restrict__ out)    // [BATCH][DOUT][WIN]
{
    __shared__ __align__(16) char smem_raw[38336];
    uint32_t* s_fhi = reinterpret_cast<uint32_t*>(smem_raw);          // [3072]
    uint32_t* s_flo = s_fhi + WIN * DIN;                              // [3072]
    float*    s_a   = reinterpret_cast<float*>(s_flo + WIN * DIN);    // [48*68]
    float*    s_b   = s_a + WIN * A_PAD;                              // [128]
    float*    s_has = s_b + DOUT;                                     // [48]
    float*    s_out = reinterpret_cast<float*>(smem_raw);             // [128][49]

    int b   = blockIdx.x;
    int tid = threadIdx.x;
    int lane = tid & 31;
    int wg   = tid >> 5;
    int g    = lane >> 2;
    int tig  = lane & 3;

    if (tid < WIN) s_has[tid] = (g_cur[b * WIN + tid] > 0) ? 1.f : 0.f;
    if (tid < DOUT) s_b[tid] = bias[tid];

    // ---- load means into temp smem (coalesced float4) ----
    {
        const float4* m4 = reinterpret_cast<const float4*>(
            g_mean + (size_t)b * WIN * DIN);
        #pragma unroll
        for (int i = tid; i < WIN * DIN / 4; i += 256) {
            int row = i >> 4;
            int c4  = i & 15;
            *reinterpret_cast<float4*>(s_a + row * A_PAD + c4 * 4) = m4[i];
        }
    }
    __syncthreads();

    // ---- split A into tf32 hi/lo in FRAGMENT order, once per element ----
    // i = ((mt*8 + ks)*32 + lane)*4 + q ; row = mt*16 + g + (q&1)*8,
    // col = ks*8 + tig + (q>>1)*4
    #pragma unroll
    for (int i = tid; i < WIN * DIN; i += 256) {
        int q     = i & 3;
        int lane2 = (i >> 2) & 31;
        int ks2   = (i >> 7) & 7;
        int mt2   = i >> 10;
        int row = mt2 * 16 + (lane2 >> 2) + (q & 1) * 8;
        int col = ks2 * 8 + (lane2 & 3) + (q >> 1) * 4;
        float v = s_a[row * A_PAD + col];
        uint32_t hi = tf32_bits(v);
        s_fhi[i] = hi;
        s_flo[i] = tf32_bits(v - __uint_as_float(hi));
    }
    __syncthreads();

    // ---- accumulators: 3 m-tiles x 2 n-tiles x 4 ----
    float acc[3][2][4];
    #pragma unroll
    for (int mt = 0; mt < 3; mt++)
        #pragma unroll
        for (int nt = 0; nt < 2; nt++)
            #pragma unroll
            for (int q = 0; q < 4; q++) acc[mt][nt][q] = 0.f;

    const uint4* fhi4 = reinterpret_cast<const uint4*>(s_fhi);
    const uint4* flo4 = reinterpret_cast<const uint4*>(s_flo);
    const uint4* whi4 = reinterpret_cast<const uint4*>(g_whi_f);
    const uint4* wlo4 = reinterpret_cast<const uint4*>(g_wlo_f);

    #pragma unroll
    for (int ks = 0; ks < 8; ks++) {
        // ---- B fragments: 2 LDG.128 from L2-resident frag planes ----
        uint4 bh = __ldg(&whi4[(wg * 8 + ks) * 32 + lane]);
        uint4 bl = __ldg(&wlo4[(wg * 8 + ks) * 32 + lane]);
        uint32_t bhi[2][2] = {{bh.x, bh.y}, {bh.z, bh.w}};
        uint32_t blo[2][2] = {{bl.x, bl.y}, {bl.z, bl.w}};

        // ---- A fragments: 6 LDS.128 (conflict-free, contiguous/warp) ----
        uint32_t ahi[3][4], alo[3][4];
        #pragma unroll
        for (int mt = 0; mt < 3; mt++) {
            uint4 h = fhi4[(mt * 8 + ks) * 32 + lane];
            uint4 l = flo4[(mt * 8 + ks) * 32 + lane];
            ahi[mt][0] = h.x; ahi[mt][1] = h.y; ahi[mt][2] = h.z; ahi[mt][3] = h.w;
            alo[mt][0] = l.x; alo[mt][1] = l.y; alo[mt][2] = l.z; alo[mt][3] = l.w;
        }

        // ---- 3xTF32 mma ----
        #pragma unroll
        for (int mt = 0; mt < 3; mt++)
            #pragma unroll
            for (int nt = 0; nt < 2; nt++) {
                mma_tf32(acc[mt][nt], ahi[mt], bhi[nt]);
                mma_tf32(acc[mt][nt], ahi[mt], blo[nt]);
                mma_tf32(acc[mt][nt], alo[mt], bhi[nt]);
            }
    }

    __syncthreads();   // frag smem dead; reuse as out staging

    // ---- stage results as out[d][w] pad-49 (+bias if nonempty) ----
    int n0 = wg * 16;
    #pragma unroll
    for (int mt = 0; mt < 3; mt++) {
        int w0 = mt * 16 + g;
        int w1 = w0 + 8;
        float h0 = s_has[w0];
        float h1 = s_has[w1];
        #pragma unroll
        for (int nt = 0; nt < 2; nt++) {
            int d = n0 + nt * 8 + tig * 2;
            float bx = s_b[d], by = s_b[d + 1];
            s_out[(d    ) * 49 + w0] = acc[mt][nt][0] + h0 * bx;
            s_out[(d + 1) * 49 + w0] = acc[mt][nt][1] + h0 * by;
            s_out[(d    ) * 49 + w1] = acc[mt][nt][2] + h1 * bx;
            s_out[(d + 1) * 49 + w1] = acc[mt][nt][3] + h1 * by;
        }
    }
    __syncthreads();

    // ---- coalesced float4 store of out[b][d][w] ----
    float* obase = out + (size_t)b * DOUT * WIN;
    #pragma unroll
    for (int it = 0; it < 6; it++) {
        int j = it * 1024 + tid * 4;
        int d = j / 48;
        int w = j - d * 48;
        const float* src = s_out + d * 49 + w;
        float4 v = make_float4(src[0], src[1], src[2], src[3]);
        *reinterpret_cast<float4*>(obase + j) = v;
    }
}

// ---------------------------------------------------------------------------
extern "C" void kernel_launch(void* const* d_in, const int* in_sizes, int n_in,
                              void* d_out, int out_size) {
    const float* input = (const float*)d_in[0];
    const float* Wm    = (const float*)d_in[1];
    const float* bias  = (const float*)d_in[2];

    const int* bi;
    const int* wi;
    int n_events;
    if (n_in >= 6 && in_sizes[3] == 1) {
        bi = (const int*)d_in[4];
        wi = (const int*)d_in[5];
        n_events = in_sizes[4];
    } else {
        bi = (const int*)d_in[3];
        wi = (const int*)d_in[4];
        n_events = in_sizes[3];
    }

    int eb = (n_events + 255) / 256;

    wsplit_frag_kernel<<<(DIN * DOUT + 255) / 256, 256>>>(Wm);
    zero_cur_kernel<<<(NSEG + 255) / 256, 256>>>();
    scatter_idx_kernel<<<eb, 256>>>(bi, wi, n_events);
    reduce_kernel<<<NSEG / 8, 256>>>(input);
    pool_gemm_kernel<<<BATCH, 256>>>(bias, (float*)d_out);
}